// round 12
// baseline (speedup 1.0000x reference)
#include <cuda_runtime.h>
#include <math.h>

#define TPB 384               // 12 warp-autonomous warps
#define NW 12
#define NUNITS 16384          // 65536 graphs / 4 per unit
#define NPU 36
#define TOTOUT 524288
#define SOFTPLUS_BIAS 0.54132485461291809f

// shared layout (float offsets)
#define OFF_WD1 0             // [64][64] swizzled (Wroot - Wrel)
#define OFF_WD2 4096
#define OFF_WR1 8192          // [64][64] swizzled Wrel
#define OFF_WR2 12288
#define OFF_WIN 16384         // [64][12]
#define OFF_WHT 17152         // [16][68]
#define OFF_BIN 18240
#define OFF_B1  18304
#define OFF_B2  18368
#define OFF_BH  18432         // [16]
#define OFF_WARP 18448
// per-warp: hws[36][68]=2448, xs[36][12]=432 (aliased as Sws[4][68]=272), csws[4][68]=272
#define WPS 3152
#define SMEM_FLOATS (OFF_WARP + NW * WPS)   // 56272 floats = 225,088 B

typedef unsigned long long u64;

__device__ __forceinline__ u64 ffma2(u64 a, u64 b, u64 c) {
    u64 d; asm("fma.rn.f32x2 %0,%1,%2,%3;" : "=l"(d) : "l"(a), "l"(b), "l"(c)); return d;
}
__device__ __forceinline__ u64 fadd2(u64 a, u64 b) {
    u64 d; asm("add.rn.f32x2 %0,%1,%2;" : "=l"(d) : "l"(a), "l"(b)); return d;
}
__device__ __forceinline__ float red2(u64 a) {
    float lo, hi; asm("mov.b64 {%0,%1},%2;" : "=f"(lo), "=f"(hi) : "l"(a)); return lo + hi;
}
__device__ __forceinline__ u64 pack2(float lo, float hi) {
    u64 v; asm("mov.b64 %0,{%1,%2};" : "=l"(v) : "f"(lo), "f"(hi)); return v;
}
__device__ __forceinline__ void unpack2(u64 v, float& lo, float& hi) {
    asm("mov.b64 {%0,%1},%2;" : "=f"(lo), "=f"(hi) : "l"(v));
}
__device__ __forceinline__ float tanh_fast(float x) {
    float y; asm("tanh.approx.f32 %0,%1;" : "=f"(y) : "f"(x)); return y;
}
__device__ __forceinline__ u64 shflx16(u64 v) {
    return __shfl_xor_sync(0xffffffffu, v, 16);
}

// rotation: row sets {2l}, {2l+1} (and xor-16 partners) conflict-free per 8-lane phase
__device__ __forceinline__ int wrot(int r) { return ((r >> 1) ^ ((r & 1) << 2)) & 7; }
__device__ __forceinline__ int wd_off(int r, int k) {
    const int c = k >> 2, j = k & 3;
    const int hc = c >> 3, c8 = c & 7;
    return r * 64 + hc * 32 + (((c8 + wrot(r)) & 7) << 2) + j;
}

// load one swizzled HALF row (32 floats = 16 u64) for this lane's k-half
__device__ __forceinline__ void load_row_half(const float* W, int r, int half, u64* wreg) {
    const int rot = wrot(r);
    const float* base = W + r * 64 + half * 32;
    #pragma unroll
    for (int j = 0; j < 8; j++) {
        const ulonglong2 v = *(const ulonglong2*)(base + (((j + rot) & 7) << 2));
        wreg[2*j] = v.x; wreg[2*j+1] = v.y;
    }
}

// split-K=2 conv, ONE node: lane reads its k-half, computes partials for own +
// partner dims, shuffle-xor(16) completes the sums. 4 accumulators only.
__device__ __forceinline__ u64 conv_one_s(const float* h0, int ko,
        const u64* wo0, const u64* wo1, const u64* wp0, const u64* wp1, u64 Sg)
{
    const float* hA = h0 + ko;
    u64 A0=0,A1=0,P0=0,P1=0;
    #pragma unroll
    for (int j = 0; j < 8; j++) {
        const ulonglong2 va = *(const ulonglong2*)(hA + j * 4);
        A0 = ffma2(wo0[2*j], va.x, A0); A0 = ffma2(wo0[2*j+1], va.y, A0);
        A1 = ffma2(wo1[2*j], va.x, A1); A1 = ffma2(wo1[2*j+1], va.y, A1);
        P0 = ffma2(wp0[2*j], va.x, P0); P0 = ffma2(wp0[2*j+1], va.y, P0);
        P1 = ffma2(wp1[2*j], va.x, P1); P1 = ffma2(wp1[2*j+1], va.y, P1);
    }
    const u64 Px0 = shflx16(P0), Px1 = shflx16(P1);
    float slo, shi; unpack2(Sg, slo, shi);
    return pack2(tanh_fast(red2(fadd2(A0, Px0)) + slo),
                 tanh_fast(red2(fadd2(A1, Px1)) + shi));
}

// One GraphConv layer, warp-local, sync-free (single non-divergent SASS stream;
// all lanes' loads of a row precede any lane's store to it by program order).
__device__ __forceinline__ void gnn_layer(float* hws, float* csws, float* Sws,
                                          int lane,
                                          const float* WR, const float* WD,
                                          const float* BB, bool first)
{
    const int d0 = lane * 2;
    const int half = lane >> 4;
    const int ko = half * 32;
    const int pd0 = (lane ^ 16) * 2;

    // ---- S-phase: S[g] at lane's own dims (d0, d0+1), written to smem ----
    {
        const int rotA = wrot(d0), rotB = wrot(d0 + 1);
        const float* wr0 = WR + d0 * 64;
        const float* wr1 = wr0 + 64;
        u64 SA[4] = {0,0,0,0}, SB[4] = {0,0,0,0};
        #pragma unroll
        for (int c = 0; c < 16; c++) {
            const int hc = (c >> 3) * 32;
            const ulonglong2 wlo = *(const ulonglong2*)(wr0 + hc + ((((c & 7) + rotA) & 7) << 2));
            const ulonglong2 whi = *(const ulonglong2*)(wr1 + hc + ((((c & 7) + rotB) & 7) << 2));
            #pragma unroll
            for (int g = 0; g < 4; g++) {
                const ulonglong2 cv = *(const ulonglong2*)(csws + g * 68 + c * 4);
                SA[g] = ffma2(wlo.x, cv.x, SA[g]); SA[g] = ffma2(wlo.y, cv.y, SA[g]);
                SB[g] = ffma2(whi.x, cv.x, SB[g]); SB[g] = ffma2(whi.y, cv.y, SB[g]);
            }
        }
        float blo, bhi; unpack2(*(const u64*)(BB + d0), blo, bhi);
        #pragma unroll
        for (int g = 0; g < 4; g++)
            *(u64*)(Sws + g * 68 + d0) = pack2(blo + red2(SA[g]), bhi + red2(SB[g]));
    }
    // (Sws entries are produced and consumed by the SAME lane -> no sync needed)

    // ---- lane-stationary weights: own + partner rows, this lane's k-half ----
    u64 wo0[16], wo1[16], wp0[16], wp1[16];
    load_row_half(WD, d0,      half, wo0);
    load_row_half(WD, d0 + 1,  half, wo1);
    load_row_half(WD, pd0,     half, wp0);
    load_row_half(WD, pd0 + 1, half, wp1);

    // ---- transform: in-place, one node at a time, store-as-you-go ----
    #pragma unroll 1
    for (int g = 0; g < 4; g++) {
        float* hb = hws + g * 9 * 68;
        const u64 Sgv = *(const u64*)(Sws + g * 68 + d0);
        if (first) {
            u64 cs = 0;
            #pragma unroll
            for (int n = 0; n < 9; n++) {
                const u64 r = conv_one_s(hb + n * 68, ko, wo0, wo1, wp0, wp1, Sgv);
                *(u64*)(hb + n * 68 + d0) = r;
                cs = fadd2(cs, r);
            }
            *(u64*)(csws + g * 68 + d0) = cs;
        } else {
            #pragma unroll
            for (int n = 1; n < 9; n++) {
                const u64 r = conv_one_s(hb + n * 68, ko, wo0, wo1, wp0, wp1, Sgv);
                *(u64*)(hb + n * 68 + d0) = r;
            }
        }
    }
}

__global__ __launch_bounds__(TPB, 1)
void gnn_kernel(const float* __restrict__ x,
                const float* __restrict__ gWin,  const float* __restrict__ gbin,
                const float* __restrict__ gW1rel, const float* __restrict__ gb1,
                const float* __restrict__ gW1root,
                const float* __restrict__ gW2rel, const float* __restrict__ gb2,
                const float* __restrict__ gW2root,
                const float* __restrict__ gWhead, const float* __restrict__ gbhead,
                float* __restrict__ out)
{
    extern __shared__ float sm[];
    const int t = threadIdx.x;
    const int lane = t & 31, w = t >> 5;
    const int d0 = lane * 2;

    // ---- one-time weight staging (swizzled) ----
    for (int i = t; i < 4096; i += TPB) {
        const int d = i >> 6, k = i & 63;
        const int so = wd_off(d, k);
        const float r1 = gW1rel[i];
        sm[OFF_WR1 + so] = r1;
        sm[OFF_WD1 + so] = gW1root[i] - r1;
        const float r2 = gW2rel[i];
        sm[OFF_WR2 + so] = r2;
        sm[OFF_WD2 + so] = gW2root[i] - r2;
    }
    for (int i = t; i < 768; i += TPB) {
        const int d = i / 12, k = i - d * 12;
        sm[OFF_WIN + i] = (k < 11) ? gWin[d * 11 + k] : 0.f;
    }
    for (int i = t; i < 1024; i += TPB) {
        const int j = i >> 7, r = i & 127, k = r >> 1, o = r & 1;
        sm[OFF_WHT + (j * 2 + o) * 68 + k] = gWhead[i];
    }
    if (t < 64) { sm[OFF_BIN + t] = gbin[t]; sm[OFF_B1 + t] = gb1[t]; sm[OFF_B2 + t] = gb2[t]; }
    if (t < 16) sm[OFF_BH + t] = gbhead[t];
    __syncthreads();

    float* const hws  = sm + OFF_WARP + w * WPS;   // [36][68]
    float* const xs   = hws + 2448;                 // [36][12]; aliased as Sws[4][68]
    float* const Sws  = xs;                         // lifetimes disjoint: xs(stage->input), Sws(S->transform)
    float* const csws = xs + 432;                   // [4][68]

    for (unsigned unit = blockIdx.x * NW + w; unit < NUNITS; unit += gridDim.x * NW) {
        // ---- stage x (396 contiguous floats, warp-coalesced) ----
        const float* xg = x + (size_t)unit * (NPU * 11);
        #pragma unroll
        for (int q = 0; q < 12; q++) {
            const int i = lane + q * 32;
            const int n = (i * 5958) >> 16;            // i/11
            xs[n * 12 + (i - n * 11)] = xg[i];
        }
        if (lane < 12) {
            const int i = lane + 384;
            const int n = (i * 5958) >> 16;
            xs[n * 12 + (i - n * 11)] = xg[i];
        }
        // pad column 11 (xs is overwritten by Sws every unit, so re-pad each time)
        xs[lane * 12 + 11] = 0.f;
        if (lane < 4) xs[(32 + lane) * 12 + 11] = 0.f;
        __syncwarp();   // (1) reconverge + xs visible; orders prior heads-reads before h writes

        // ---- input layer: dims (d0,d0+1) stationary; colsum in regs ----
        {
            u64 wiA[6], wiB[6];
            const float* w0 = sm + OFF_WIN + d0 * 12;
            #pragma unroll
            for (int q = 0; q < 3; q++) {
                const ulonglong2 a = *(const ulonglong2*)(w0 + q * 4);
                const ulonglong2 b = *(const ulonglong2*)(w0 + 12 + q * 4);
                wiA[2*q] = a.x; wiA[2*q+1] = a.y;
                wiB[2*q] = b.x; wiB[2*q+1] = b.y;
            }
            float blo, bhi; unpack2(*(const u64*)(sm + OFF_BIN + d0), blo, bhi);
            #pragma unroll 1
            for (int g = 0; g < 4; g++) {
                u64 cs = 0;
                const float* xb = xs + g * 9 * 12;
                float* hb = hws + g * 9 * 68;
                #pragma unroll
                for (int pp = 0; pp < 4; pp++) {
                    const float* x0 = xb + 2 * pp * 12;
                    const float* x1 = x0 + 12;
                    u64 A=0, B=0, C=0, D=0;
                    #pragma unroll
                    for (int q = 0; q < 3; q++) {
                        const ulonglong2 v0 = *(const ulonglong2*)(x0 + q * 4);
                        const ulonglong2 v1 = *(const ulonglong2*)(x1 + q * 4);
                        A = ffma2(wiA[2*q], v0.x, A); A = ffma2(wiA[2*q+1], v0.y, A);
                        B = ffma2(wiB[2*q], v0.x, B); B = ffma2(wiB[2*q+1], v0.y, B);
                        C = ffma2(wiA[2*q], v1.x, C); C = ffma2(wiA[2*q+1], v1.y, C);
                        D = ffma2(wiB[2*q], v1.x, D); D = ffma2(wiB[2*q+1], v1.y, D);
                    }
                    const u64 r0 = pack2(red2(A) + blo, red2(B) + bhi);
                    const u64 r1 = pack2(red2(C) + blo, red2(D) + bhi);
                    *(u64*)(hb + (2*pp) * 68 + d0) = r0;
                    *(u64*)(hb + (2*pp+1) * 68 + d0) = r1;
                    cs = fadd2(cs, fadd2(r0, r1));
                }
                {
                    const float* x0 = xb + 8 * 12;
                    u64 A=0, B=0;
                    #pragma unroll
                    for (int q = 0; q < 3; q++) {
                        const ulonglong2 v0 = *(const ulonglong2*)(x0 + q * 4);
                        A = ffma2(wiA[2*q], v0.x, A); A = ffma2(wiA[2*q+1], v0.y, A);
                        B = ffma2(wiB[2*q], v0.x, B); B = ffma2(wiB[2*q+1], v0.y, B);
                    }
                    const u64 r0 = pack2(red2(A) + blo, red2(B) + bhi);
                    *(u64*)(hb + 8 * 68 + d0) = r0;
                    cs = fadd2(cs, r0);
                }
                *(u64*)(csws + g * 68 + d0) = cs;
            }
        }
        __syncwarp();   // (2) h + csws cross-lane visible for L1 (also: xs reads done before Sws writes)

        gnn_layer(hws, csws, Sws, lane, sm + OFF_WR1, sm + OFF_WD1, sm + OFF_B1, true);
        __syncwarp();   // (3) L1 h + csws visible for L2

        gnn_layer(hws, csws, Sws, lane, sm + OFF_WR2, sm + OFF_WD2, sm + OFF_B2, false);
        __syncwarp();   // (4) L2 h visible for heads

        // ---- heads: lane = (graph-half, node j, output o); 2 graphs per lane ----
        {
            const int gh = lane >> 4, j = (lane >> 1) & 7, o = lane & 1;
            const float* whr = sm + OFF_WHT + (j * 2 + o) * 68;
            const float bh = sm[OFF_BH + j * 2 + o];
            #pragma unroll
            for (int gl = 0; gl < 2; gl++) {
                const int graph = gl * 2 + gh;
                const float* hr = hws + (graph * 9 + j + 1) * 68;
                u64 A0=0, A1=0, A2=0, A3=0;
                #pragma unroll
                for (int q = 0; q < 8; q++) {
                    const ulonglong2 wv  = *(const ulonglong2*)(whr + q * 8);
                    const ulonglong2 wv2 = *(const ulonglong2*)(whr + q * 8 + 4);
                    const ulonglong2 hv  = *(const ulonglong2*)(hr + q * 8);
                    const ulonglong2 hv2 = *(const ulonglong2*)(hr + q * 8 + 4);
                    A0 = ffma2(wv.x,  hv.x,  A0);
                    A1 = ffma2(wv.y,  hv.y,  A1);
                    A2 = ffma2(wv2.x, hv2.x, A2);
                    A3 = ffma2(wv2.y, hv2.y, A3);
                }
                const float r = bh + red2(fadd2(fadd2(A0, A1), fadd2(A2, A3)));
                const size_t gi = (size_t)(unit * 4 + graph) * 8 + j;
                if (o == 0) {
                    out[gi] = r;
                } else {
                    const float z = r + SOFTPLUS_BIAS;
                    const float sp = (z > 20.f) ? z : log1pf(__expf(z));
                    out[TOTOUT + gi] = fmaxf(sp, 1e-4f);
                }
            }
        }
        // next unit's staging sync (1) orders heads-reads before h overwrite
    }
}

extern "C" void kernel_launch(void* const* d_in, const int* in_sizes, int n_in,
                              void* d_out, int out_size)
{
    (void)in_sizes; (void)n_in; (void)out_size;
    const float* x      = (const float*)d_in[0];
    // d_in[1] = edge_index: dense 9-node graphs, structurally known -> unused
    const float* W_in   = (const float*)d_in[2];
    const float* b_in   = (const float*)d_in[3];
    const float* W1_rel = (const float*)d_in[4];
    const float* b1     = (const float*)d_in[5];
    const float* W1_root= (const float*)d_in[6];
    const float* W2_rel = (const float*)d_in[7];
    const float* b2     = (const float*)d_in[8];
    const float* W2_root= (const float*)d_in[9];
    const float* W_head = (const float*)d_in[10];
    const float* b_head = (const float*)d_in[11];
    float* out = (float*)d_out;

    int nsm = 148;
    cudaDeviceGetAttribute(&nsm, cudaDevAttrMultiProcessorCount, 0);

    const int smem = SMEM_FLOATS * 4;
    cudaFuncSetAttribute(gnn_kernel, cudaFuncAttributeMaxDynamicSharedMemorySize, smem);
    gnn_kernel<<<nsm, TPB, smem>>>(x, W_in, b_in, W1_rel, b1, W1_root,
                                   W2_rel, b2, W2_root, W_head, b_head, out);
}

// round 13
// speedup vs baseline: 1.0673x; 1.0673x over previous
#include <cuda_runtime.h>
#include <math.h>

#define TPB 384               // 12 warp-autonomous warps
#define NW 12
#define NUNITS 16384          // 65536 graphs / 4 per unit
#define NPU 36
#define TOTOUT 524288
#define SOFTPLUS_BIAS 0.54132485461291809f

// shared layout (float offsets)
#define OFF_WD1 0             // [64][64] swizzled (Wroot - Wrel)
#define OFF_WD2 4096
#define OFF_WR1 8192          // [64][64] swizzled Wrel
#define OFF_WR2 12288
#define OFF_WIN 16384         // [64][12]
#define OFF_WHT 17152         // [16][68]
#define OFF_BIN 18240
#define OFF_B1  18304
#define OFF_B2  18368
#define OFF_BH  18432         // [16]
#define OFF_WARP 18448
// per-warp: hws[36][68]=2448, xs[36][12]=432 (aliased as Sws[4][68]=272), csws[4][68]=272
#define WPS 3152
#define SMEM_FLOATS (OFF_WARP + NW * WPS)   // 56272 floats = 225,088 B

typedef unsigned long long u64;

__device__ __forceinline__ u64 ffma2(u64 a, u64 b, u64 c) {
    u64 d; asm("fma.rn.f32x2 %0,%1,%2,%3;" : "=l"(d) : "l"(a), "l"(b), "l"(c)); return d;
}
__device__ __forceinline__ u64 fadd2(u64 a, u64 b) {
    u64 d; asm("add.rn.f32x2 %0,%1,%2;" : "=l"(d) : "l"(a), "l"(b)); return d;
}
__device__ __forceinline__ float red2(u64 a) {
    float lo, hi; asm("mov.b64 {%0,%1},%2;" : "=f"(lo), "=f"(hi) : "l"(a)); return lo + hi;
}
__device__ __forceinline__ u64 pack2(float lo, float hi) {
    u64 v; asm("mov.b64 %0,{%1,%2};" : "=l"(v) : "f"(lo), "f"(hi)); return v;
}
__device__ __forceinline__ void unpack2(u64 v, float& lo, float& hi) {
    asm("mov.b64 {%0,%1},%2;" : "=f"(lo), "=f"(hi) : "l"(v));
}
__device__ __forceinline__ float tanh_fast(float x) {
    float y; asm("tanh.approx.f32 %0,%1;" : "=f"(y) : "f"(x)); return y;
}
__device__ __forceinline__ u64 shflx16(u64 v) {
    return __shfl_xor_sync(0xffffffffu, v, 16);
}

// rotation: row sets {2l}, {2l+1} (and xor-16 partners) conflict-free per 8-lane phase
__device__ __forceinline__ int wrot(int r) { return ((r >> 1) ^ ((r & 1) << 2)) & 7; }
__device__ __forceinline__ int wd_off(int r, int k) {
    const int c = k >> 2, j = k & 3;
    const int hc = c >> 3, c8 = c & 7;
    return r * 64 + hc * 32 + (((c8 + wrot(r)) & 7) << 2) + j;
}

// load one swizzled HALF row (32 floats = 16 u64) for this lane's k-half
__device__ __forceinline__ void load_row_half(const float* W, int r, int half, u64* wreg) {
    const int rot = wrot(r);
    const float* base = W + r * 64 + half * 32;
    #pragma unroll
    for (int j = 0; j < 8; j++) {
        const ulonglong2 v = *(const ulonglong2*)(base + (((j + rot) & 7) << 2));
        wreg[2*j] = v.x; wreg[2*j+1] = v.y;
    }
}

// split-K=2 conv, TWO consecutive nodes (8 accumulator chains for ILP):
// lane reads its k-half of each node row, computes partials for own + partner
// dims; shuffle-xor(16) completes the sums.
__device__ __forceinline__ void conv_pair_s(const float* h0, int ko,
        const u64* wo0, const u64* wo1, const u64* wp0, const u64* wp1,
        u64 Sg, u64& r0, u64& r1)
{
    const float* hA = h0 + ko;
    const float* hB = h0 + 68 + ko;
    u64 A0=0,A1=0,P0=0,P1=0,B0=0,B1=0,Q0=0,Q1=0;
    #pragma unroll
    for (int j = 0; j < 8; j++) {
        const ulonglong2 va = *(const ulonglong2*)(hA + j * 4);
        const ulonglong2 vb = *(const ulonglong2*)(hB + j * 4);
        A0 = ffma2(wo0[2*j], va.x, A0); A0 = ffma2(wo0[2*j+1], va.y, A0);
        A1 = ffma2(wo1[2*j], va.x, A1); A1 = ffma2(wo1[2*j+1], va.y, A1);
        P0 = ffma2(wp0[2*j], va.x, P0); P0 = ffma2(wp0[2*j+1], va.y, P0);
        P1 = ffma2(wp1[2*j], va.x, P1); P1 = ffma2(wp1[2*j+1], va.y, P1);
        B0 = ffma2(wo0[2*j], vb.x, B0); B0 = ffma2(wo0[2*j+1], vb.y, B0);
        B1 = ffma2(wo1[2*j], vb.x, B1); B1 = ffma2(wo1[2*j+1], vb.y, B1);
        Q0 = ffma2(wp0[2*j], vb.x, Q0); Q0 = ffma2(wp0[2*j+1], vb.y, Q0);
        Q1 = ffma2(wp1[2*j], vb.x, Q1); Q1 = ffma2(wp1[2*j+1], vb.y, Q1);
    }
    float slo, shi; unpack2(Sg, slo, shi);
    // stagger shuffles to cap transient pressure
    const u64 s0 = fadd2(A0, shflx16(P0));
    const u64 s1 = fadd2(A1, shflx16(P1));
    r0 = pack2(tanh_fast(red2(s0) + slo), tanh_fast(red2(s1) + shi));
    const u64 s2 = fadd2(B0, shflx16(Q0));
    const u64 s3 = fadd2(B1, shflx16(Q1));
    r1 = pack2(tanh_fast(red2(s2) + slo), tanh_fast(red2(s3) + shi));
}

__device__ __forceinline__ u64 conv_one_s(const float* h0, int ko,
        const u64* wo0, const u64* wo1, const u64* wp0, const u64* wp1, u64 Sg)
{
    const float* hA = h0 + ko;
    u64 A0=0,A1=0,P0=0,P1=0;
    #pragma unroll
    for (int j = 0; j < 8; j++) {
        const ulonglong2 va = *(const ulonglong2*)(hA + j * 4);
        A0 = ffma2(wo0[2*j], va.x, A0); A0 = ffma2(wo0[2*j+1], va.y, A0);
        A1 = ffma2(wo1[2*j], va.x, A1); A1 = ffma2(wo1[2*j+1], va.y, A1);
        P0 = ffma2(wp0[2*j], va.x, P0); P0 = ffma2(wp0[2*j+1], va.y, P0);
        P1 = ffma2(wp1[2*j], va.x, P1); P1 = ffma2(wp1[2*j+1], va.y, P1);
    }
    const u64 s0 = fadd2(A0, shflx16(P0));
    const u64 s1 = fadd2(A1, shflx16(P1));
    float slo, shi; unpack2(Sg, slo, shi);
    return pack2(tanh_fast(red2(s0) + slo), tanh_fast(red2(s1) + shi));
}

// One GraphConv layer, warp-local, sync-free (single non-divergent SASS stream;
// all lanes' loads of a row precede any lane's store to it by program order).
__device__ __forceinline__ void gnn_layer(float* hws, float* csws, float* Sws,
                                          int lane,
                                          const float* WR, const float* WD,
                                          const float* BB, bool first)
{
    const int d0 = lane * 2;
    const int half = lane >> 4;
    const int ko = half * 32;
    const int pd0 = (lane ^ 16) * 2;

    // ---- S-phase: S[g] at lane's own dims (d0, d0+1), stored to smem ----
    {
        const int rotA = wrot(d0), rotB = wrot(d0 + 1);
        const float* wr0 = WR + d0 * 64;
        const float* wr1 = wr0 + 64;
        u64 SA[4] = {0,0,0,0}, SB[4] = {0,0,0,0};
        #pragma unroll
        for (int c = 0; c < 16; c++) {
            const int hc = (c >> 3) * 32;
            const ulonglong2 wlo = *(const ulonglong2*)(wr0 + hc + ((((c & 7) + rotA) & 7) << 2));
            const ulonglong2 whi = *(const ulonglong2*)(wr1 + hc + ((((c & 7) + rotB) & 7) << 2));
            #pragma unroll
            for (int g = 0; g < 4; g++) {
                const ulonglong2 cv = *(const ulonglong2*)(csws + g * 68 + c * 4);
                SA[g] = ffma2(wlo.x, cv.x, SA[g]); SA[g] = ffma2(wlo.y, cv.y, SA[g]);
                SB[g] = ffma2(whi.x, cv.x, SB[g]); SB[g] = ffma2(whi.y, cv.y, SB[g]);
            }
        }
        float blo, bhi; unpack2(*(const u64*)(BB + d0), blo, bhi);
        #pragma unroll
        for (int g = 0; g < 4; g++)
            *(u64*)(Sws + g * 68 + d0) = pack2(blo + red2(SA[g]), bhi + red2(SB[g]));
    }
    // (Sws entries produced and consumed by the SAME lane -> no sync needed)

    // ---- lane-stationary weights: own + partner rows, this lane's k-half ----
    u64 wo0[16], wo1[16], wp0[16], wp1[16];
    load_row_half(WD, d0,      half, wo0);
    load_row_half(WD, d0 + 1,  half, wo1);
    load_row_half(WD, pd0,     half, wp0);
    load_row_half(WD, pd0 + 1, half, wp1);

    // ---- transform: in-place, node pairs, store-as-you-go ----
    #pragma unroll 1
    for (int g = 0; g < 4; g++) {
        float* hb = hws + g * 9 * 68;
        const u64 Sgv = *(const u64*)(Sws + g * 68 + d0);
        if (first) {
            u64 cs;
            {
                u64 r0, r1;
                conv_pair_s(hb + 0 * 68, ko, wo0, wo1, wp0, wp1, Sgv, r0, r1);
                *(u64*)(hb + 0 * 68 + d0) = r0;
                *(u64*)(hb + 1 * 68 + d0) = r1;
                cs = fadd2(r0, r1);
            }
            #pragma unroll
            for (int p = 1; p < 4; p++) {
                u64 r0, r1;
                conv_pair_s(hb + (2 * p) * 68, ko, wo0, wo1, wp0, wp1, Sgv, r0, r1);
                *(u64*)(hb + (2 * p) * 68 + d0) = r0;
                *(u64*)(hb + (2 * p + 1) * 68 + d0) = r1;
                cs = fadd2(cs, fadd2(r0, r1));
            }
            {
                const u64 r8 = conv_one_s(hb + 8 * 68, ko, wo0, wo1, wp0, wp1, Sgv);
                *(u64*)(hb + 8 * 68 + d0) = r8;
                cs = fadd2(cs, r8);
            }
            *(u64*)(csws + g * 68 + d0) = cs;
        } else {
            #pragma unroll
            for (int p = 0; p < 4; p++) {
                u64 r0, r1;
                conv_pair_s(hb + (2 * p + 1) * 68, ko, wo0, wo1, wp0, wp1, Sgv, r0, r1);
                *(u64*)(hb + (2 * p + 1) * 68 + d0) = r0;
                *(u64*)(hb + (2 * p + 2) * 68 + d0) = r1;
            }
        }
    }
}

__global__ __launch_bounds__(TPB, 1)
void gnn_kernel(const float* __restrict__ x,
                const float* __restrict__ gWin,  const float* __restrict__ gbin,
                const float* __restrict__ gW1rel, const float* __restrict__ gb1,
                const float* __restrict__ gW1root,
                const float* __restrict__ gW2rel, const float* __restrict__ gb2,
                const float* __restrict__ gW2root,
                const float* __restrict__ gWhead, const float* __restrict__ gbhead,
                float* __restrict__ out)
{
    extern __shared__ float sm[];
    const int t = threadIdx.x;
    const int lane = t & 31, w = t >> 5;
    const int d0 = lane * 2;

    // ---- one-time weight staging (swizzled) ----
    for (int i = t; i < 4096; i += TPB) {
        const int d = i >> 6, k = i & 63;
        const int so = wd_off(d, k);
        const float r1 = gW1rel[i];
        sm[OFF_WR1 + so] = r1;
        sm[OFF_WD1 + so] = gW1root[i] - r1;
        const float r2 = gW2rel[i];
        sm[OFF_WR2 + so] = r2;
        sm[OFF_WD2 + so] = gW2root[i] - r2;
    }
    for (int i = t; i < 768; i += TPB) {
        const int d = i / 12, k = i - d * 12;
        sm[OFF_WIN + i] = (k < 11) ? gWin[d * 11 + k] : 0.f;
    }
    for (int i = t; i < 1024; i += TPB) {
        const int j = i >> 7, r = i & 127, k = r >> 1, o = r & 1;
        sm[OFF_WHT + (j * 2 + o) * 68 + k] = gWhead[i];
    }
    if (t < 64) { sm[OFF_BIN + t] = gbin[t]; sm[OFF_B1 + t] = gb1[t]; sm[OFF_B2 + t] = gb2[t]; }
    if (t < 16) sm[OFF_BH + t] = gbhead[t];
    __syncthreads();

    float* const hws  = sm + OFF_WARP + w * WPS;   // [36][68]
    float* const xs   = hws + 2448;                 // [36][12]; aliased as Sws[4][68]
    float* const Sws  = xs;                         // lifetimes disjoint: xs(stage->input), Sws(S->transform)
    float* const csws = xs + 432;                   // [4][68]

    for (unsigned unit = blockIdx.x * NW + w; unit < NUNITS; unit += gridDim.x * NW) {
        // ---- stage x (396 contiguous floats, warp-coalesced) ----
        const float* xg = x + (size_t)unit * (NPU * 11);
        #pragma unroll
        for (int q = 0; q < 12; q++) {
            const int i = lane + q * 32;
            const int n = (i * 5958) >> 16;            // i/11
            xs[n * 12 + (i - n * 11)] = xg[i];
        }
        if (lane < 12) {
            const int i = lane + 384;
            const int n = (i * 5958) >> 16;
            xs[n * 12 + (i - n * 11)] = xg[i];
        }
        // re-pad column 11 every unit (xs region is reused as Sws)
        xs[lane * 12 + 11] = 0.f;
        if (lane < 4) xs[(32 + lane) * 12 + 11] = 0.f;
        __syncwarp();   // (1) reconverge + xs visible; orders prior heads-reads before h writes

        // ---- input layer: dims (d0,d0+1) stationary; colsum in regs ----
        {
            u64 wiA[6], wiB[6];
            const float* w0 = sm + OFF_WIN + d0 * 12;
            #pragma unroll
            for (int q = 0; q < 3; q++) {
                const ulonglong2 a = *(const ulonglong2*)(w0 + q * 4);
                const ulonglong2 b = *(const ulonglong2*)(w0 + 12 + q * 4);
                wiA[2*q] = a.x; wiA[2*q+1] = a.y;
                wiB[2*q] = b.x; wiB[2*q+1] = b.y;
            }
            float blo, bhi; unpack2(*(const u64*)(sm + OFF_BIN + d0), blo, bhi);
            #pragma unroll 1
            for (int g = 0; g < 4; g++) {
                u64 cs = 0;
                const float* xb = xs + g * 9 * 12;
                float* hb = hws + g * 9 * 68;
                #pragma unroll
                for (int pp = 0; pp < 4; pp++) {
                    const float* x0 = xb + 2 * pp * 12;
                    const float* x1 = x0 + 12;
                    u64 A=0, B=0, C=0, D=0;
                    #pragma unroll
                    for (int q = 0; q < 3; q++) {
                        const ulonglong2 v0 = *(const ulonglong2*)(x0 + q * 4);
                        const ulonglong2 v1 = *(const ulonglong2*)(x1 + q * 4);
                        A = ffma2(wiA[2*q], v0.x, A); A = ffma2(wiA[2*q+1], v0.y, A);
                        B = ffma2(wiB[2*q], v0.x, B); B = ffma2(wiB[2*q+1], v0.y, B);
                        C = ffma2(wiA[2*q], v1.x, C); C = ffma2(wiA[2*q+1], v1.y, C);
                        D = ffma2(wiB[2*q], v1.x, D); D = ffma2(wiB[2*q+1], v1.y, D);
                    }
                    const u64 r0 = pack2(red2(A) + blo, red2(B) + bhi);
                    const u64 r1 = pack2(red2(C) + blo, red2(D) + bhi);
                    *(u64*)(hb + (2*pp) * 68 + d0) = r0;
                    *(u64*)(hb + (2*pp+1) * 68 + d0) = r1;
                    cs = fadd2(cs, fadd2(r0, r1));
                }
                {
                    const float* x0 = xb + 8 * 12;
                    u64 A=0, B=0;
                    #pragma unroll
                    for (int q = 0; q < 3; q++) {
                        const ulonglong2 v0 = *(const ulonglong2*)(x0 + q * 4);
                        A = ffma2(wiA[2*q], v0.x, A); A = ffma2(wiA[2*q+1], v0.y, A);
                        B = ffma2(wiB[2*q], v0.x, B); B = ffma2(wiB[2*q+1], v0.y, B);
                    }
                    const u64 r0 = pack2(red2(A) + blo, red2(B) + bhi);
                    *(u64*)(hb + 8 * 68 + d0) = r0;
                    cs = fadd2(cs, r0);
                }
                *(u64*)(csws + g * 68 + d0) = cs;
            }
        }
        __syncwarp();   // (2) h + csws cross-lane visible for L1 (xs reads done before Sws writes)

        gnn_layer(hws, csws, Sws, lane, sm + OFF_WR1, sm + OFF_WD1, sm + OFF_B1, true);
        __syncwarp();   // (3) L1 h + csws visible for L2

        gnn_layer(hws, csws, Sws, lane, sm + OFF_WR2, sm + OFF_WD2, sm + OFF_B2, false);
        __syncwarp();   // (4) L2 h visible for heads

        // ---- heads: lane = (graph-half, node j, output o); 2 graphs per lane ----
        {
            const int gh = lane >> 4, j = (lane >> 1) & 7, o = lane & 1;
            const float* whr = sm + OFF_WHT + (j * 2 + o) * 68;
            const float bh = sm[OFF_BH + j * 2 + o];
            #pragma unroll
            for (int gl = 0; gl < 2; gl++) {
                const int graph = gl * 2 + gh;
                const float* hr = hws + (graph * 9 + j + 1) * 68;
                u64 A0=0, A1=0, A2=0, A3=0;
                #pragma unroll
                for (int q = 0; q < 8; q++) {
                    const ulonglong2 wv  = *(const ulonglong2*)(whr + q * 8);
                    const ulonglong2 wv2 = *(const ulonglong2*)(whr + q * 8 + 4);
                    const ulonglong2 hv  = *(const ulonglong2*)(hr + q * 8);
                    const ulonglong2 hv2 = *(const ulonglong2*)(hr + q * 8 + 4);
                    A0 = ffma2(wv.x,  hv.x,  A0);
                    A1 = ffma2(wv.y,  hv.y,  A1);
                    A2 = ffma2(wv2.x, hv2.x, A2);
                    A3 = ffma2(wv2.y, hv2.y, A3);
                }
                const float r = bh + red2(fadd2(fadd2(A0, A1), fadd2(A2, A3)));
                const size_t gi = (size_t)(unit * 4 + graph) * 8 + j;
                if (o == 0) {
                    out[gi] = r;
                } else {
                    const float z = r + SOFTPLUS_BIAS;
                    const float sp = (z > 20.f) ? z : log1pf(__expf(z));
                    out[TOTOUT + gi] = fmaxf(sp, 1e-4f);
                }
            }
        }
        // next unit's staging sync (1) orders heads-reads before h overwrite
    }
}

extern "C" void kernel_launch(void* const* d_in, const int* in_sizes, int n_in,
                              void* d_out, int out_size)
{
    (void)in_sizes; (void)n_in; (void)out_size;
    const float* x      = (const float*)d_in[0];
    // d_in[1] = edge_index: dense 9-node graphs, structurally known -> unused
    const float* W_in   = (const float*)d_in[2];
    const float* b_in   = (const float*)d_in[3];
    const float* W1_rel = (const float*)d_in[4];
    const float* b1     = (const float*)d_in[5];
    const float* W1_root= (const float*)d_in[6];
    const float* W2_rel = (const float*)d_in[7];
    const float* b2     = (const float*)d_in[8];
    const float* W2_root= (const float*)d_in[9];
    const float* W_head = (const float*)d_in[10];
    const float* b_head = (const float*)d_in[11];
    float* out = (float*)d_out;

    int nsm = 148;
    cudaDeviceGetAttribute(&nsm, cudaDevAttrMultiProcessorCount, 0);

    const int smem = SMEM_FLOATS * 4;
    cudaFuncSetAttribute(gnn_kernel, cudaFuncAttributeMaxDynamicSharedMemorySize, smem);
    gnn_kernel<<<nsm, TPB, smem>>>(x, W_in, b_in, W1_rel, b1, W1_root,
                                   W2_rel, b2, W2_root, W_head, b_head, out);
}